// round 8
// baseline (speedup 1.0000x reference)
#include <cuda_runtime.h>

#define LBL   64
#define MAXT  200000
#define S_CH  500
#define MAXK  512

// scratch (static device globals — no allocation)
// g_v2: TRANSPOSED viterbi vars: g_v2[n*MAXT + t] = V[t+1][n] (v after step t)
__device__ float         g_v2[(size_t)LBL * MAXT];
__device__ unsigned char g_bp[(size_t)MAXT * LBL];  // bp rows, row 0 unused
__device__ unsigned char g_H[MAXK * LBL];           // per-chunk composed maps
__device__ int           g_E[MAXK + 2];             // boundary path values
__device__ int           g_best;

// ---------------------------------------------------------------------------
// Phase 1: serial forward pass. 1 block, 128 threads (4 warps, 1 per SMSP).
// warp w handles tags n = 16w..16w+15; 2 lanes per tag (q=0,1), 32 prevs/lane.
// v kept in TWO shared copies with a 4-float skew so each LDS.128 (one
// broadcast address per q-group) hits disjoint bank quads -> 1 wavefront:
//   svA = svbuf[cur*64 + n]          (q=0 reads prevs 0..31 at banks 4j..4j+3)
//   svB = svbuf[128 + cur*68 + 4+n]  (q=1 reads prevs 32..63 at banks 4j+4.. /
//                                     4j+8.. depending on parity; disjoint)
// Both lanes hold vn after the SHFL; q=0 stores svA, q=1 stores svB + g_v2.
// Chain: LDS -> add/max tree (skewed: late chunks shallow) -> +feat -> SHFL
// -> FMNMX -> STS -> BAR(nw=4). Emission folded pre-shuffle (bit-exact:
// fmax(a+f,b+f) == fmax(a,b)+f, monotone rounding). Body otherwise R4-exact
// (R5-R7: batching/pipelining/packed-math all regressed — do not reapply).
// ---------------------------------------------------------------------------
__global__ void __launch_bounds__(128, 1)
fwd_kernel(const float* __restrict__ feats, const float* __restrict__ trans, int T)
{
    // svA[2][64] at [0..128), svB[2][68] at [128..264)
    __shared__ __align__(16) float svbuf[264];
    __shared__ __align__(16) float fsh[2][64 * LBL];   // 2 x 16KB feat chunks

    const int tid  = threadIdx.x;
    const int w    = tid >> 5;
    const int lane = tid & 31;
    const int k    = lane >> 1;       // tag within warp (0..15)
    const int q    = lane & 1;        // prev-half (0:|0..31|, 1:|32..63|)
    const int n    = w * 16 + k;

    // preload this lane's transition segment T[n][q*32 .. q*32+31] (8 float4)
    const float4* trr = reinterpret_cast<const float4*>(trans + n * 64 + q * 32);
    const float4 t0 = trr[0], t1 = trr[1], t2 = trr[2], t3 = trr[3];
    const float4 t4 = trr[4], t5 = trr[5], t6 = trr[6], t7 = trr[7];

    // per-lane read base (float4-aligned) and store address, per parity
    // q=0: read svbuf + cur*64            store svbuf + nxt*64 + n
    // q=1: read svbuf + 128 + cur*68 + 36 store svbuf + 128 + nxt*68 + 4 + n
    const float4* rd0 = reinterpret_cast<const float4*>(
        q ? (svbuf + 128 + 0 * 68 + 36) : (svbuf + 0 * 64));
    const float4* rd1 = reinterpret_cast<const float4*>(
        q ? (svbuf + 128 + 1 * 68 + 36) : (svbuf + 1 * 64));
    float* st0 = q ? (svbuf + 128 + 0 * 68 + 4 + n) : (svbuf + 0 * 64 + n);
    float* st1 = q ? (svbuf + 128 + 1 * 68 + 4 + n) : (svbuf + 1 * 64 + n);

    if (tid < 64) {
        const float iv = (tid == 62) ? 0.0f : -10000.0f;   // START=62
        svbuf[tid]            = iv;   // svA[0]
        svbuf[128 + 4 + tid]  = iv;   // svB[0]
    }

    const int nch = (T + 63) >> 6;
    const int totElems = T * LBL;

    // prefetch one 16KB chunk (64 steps) with cp.async
    auto prefetch = [&](int ch, int buf) {
        const float* src = feats + ch * 4096;
#pragma unroll
        for (int i = 0; i < 8; i++) {
            int e = tid + i * 128;                 // 16B units within chunk
            if (ch * 4096 + e * 4 + 3 < totElems) {
                unsigned saddr = (unsigned)__cvta_generic_to_shared(&fsh[buf][e * 4]);
                asm volatile("cp.async.cg.shared.global [%0], [%1], 16;"
                             :: "r"(saddr), "l"(src + e * 4));
            }
        }
        asm volatile("cp.async.commit_group;" ::: "memory");
    };

    prefetch(0, 0);
    if (nch > 1) prefetch(1, 1); else asm volatile("cp.async.commit_group;" ::: "memory");
    __syncthreads();

    // one step: read RD (this parity), store to ST (next parity)
    #define FWD_BODY(RD, ST, FCUR, VN)                                                     \
    {                                                                                      \
        const float4 a0 = (RD)[0], a1 = (RD)[1], a2 = (RD)[2], a3 = (RD)[3];               \
        const float4 a4 = (RD)[4], a5 = (RD)[5], a6 = (RD)[6], a7 = (RD)[7];               \
        float m0 = fmaxf(fmaxf(a0.x + t0.x, a0.y + t0.y), fmaxf(a0.z + t0.z, a0.w + t0.w));\
        float m1 = fmaxf(fmaxf(a1.x + t1.x, a1.y + t1.y), fmaxf(a1.z + t1.z, a1.w + t1.w));\
        float m2 = fmaxf(fmaxf(a2.x + t2.x, a2.y + t2.y), fmaxf(a2.z + t2.z, a2.w + t2.w));\
        float m3 = fmaxf(fmaxf(a3.x + t3.x, a3.y + t3.y), fmaxf(a3.z + t3.z, a3.w + t3.w));\
        float m4 = fmaxf(fmaxf(a4.x + t4.x, a4.y + t4.y), fmaxf(a4.z + t4.z, a4.w + t4.w));\
        float m5 = fmaxf(fmaxf(a5.x + t5.x, a5.y + t5.y), fmaxf(a5.z + t5.z, a5.w + t5.w));\
        float m6 = fmaxf(fmaxf(a6.x + t6.x, a6.y + t6.y), fmaxf(a6.z + t6.z, a6.w + t6.w));\
        float m7 = fmaxf(fmaxf(a7.x + t7.x, a7.y + t7.y), fmaxf(a7.z + t7.z, a7.w + t7.w));\
        /* skewed tree: late-returning chunks combined shallow */                          \
        float mm = fmaxf(fmaxf(fmaxf(fmaxf(fmaxf(m0, m1), fmaxf(m2, m3)),                  \
                                     fmaxf(m4, m5)), m6), m7);                             \
        mm += (FCUR);                                                                      \
        const float other = __shfl_xor_sync(0xffffffffu, mm, 1);                           \
        VN = fmaxf(mm, other);                                                             \
        *(ST) = VN;                                                                        \
        __syncthreads();                                                                   \
    }

    for (int ch = 0; ch < nch; ch++) {
        asm volatile("cp.async.wait_group 1;" ::: "memory");
        __syncthreads();
        const float* fb  = fsh[ch & 1] + n;
        float*       gvp = g_v2 + (size_t)n * MAXT + (ch << 6);   // q=1 store row
        const int steps = min(64, T - (ch << 6));
#pragma unroll 2
        for (int i = 0; i < steps; i++) {
            float vn;
            if ((i & 1) == 0) { FWD_BODY(rd0, st1, fb[i << 6], vn) }
            else              { FWD_BODY(rd1, st0, fb[i << 6], vn) }
            if (q == 1) gvp[i] = vn;    // off-chain global store
        }
        if (ch + 2 < nch) prefetch(ch + 2, ch & 1);
        else asm volatile("cp.async.commit_group;" ::: "memory");
    }
    #undef FWD_BODY
}

// ---------------------------------------------------------------------------
// Phase 2: recompute backpointers for all t in [1, T-1], fully parallel.
// Block covers 64 consecutive t. Stages a 64x64 v-tile (tag-major g_v2 rows,
// coalesced) + transposed trans tile in shared. Strict '>' ascending p ==
// jnp.argmax first-index tie-break; adds bit-exact vs reference.
// ---------------------------------------------------------------------------
__global__ void __launch_bounds__(256)
bp_kernel(const float* __restrict__ trans, int T)
{
    __shared__ float trsT[64 * 65];   // trsT[p*65+n] = trans[n][p]
    __shared__ float vt[64][65];      // vt[p][tl] = V[tb+tl+1][p]

    const int tid = threadIdx.x;
    for (int x = tid; x < 4096; x += 256)
        trsT[(x & 63) * 65 + (x >> 6)] = trans[x];

    const int tb = blockIdx.x << 6;       // covers bp rows t = tb+1 .. tb+64
    const int tl = tid & 63;
    for (int p = tid >> 6; p < 64; p += 4) {
        const int tg = tb + tl;           // index into g_v2 time axis (= t-1)
        vt[p][tl] = (tg <= T - 2) ? g_v2[(size_t)p * MAXT + tg] : 0.0f;
    }
    __syncthreads();

    const int tt = tid >> 6, n = tid & 63;
#pragma unroll 1
    for (int r = 0; r < 16; r++) {
        const int lt = tt + (r << 2);     // local time 0..63
        const int t  = tb + 1 + lt;
        if (t > T - 1) continue;
        float m = -3.4e38f;
        int bi = 0;
#pragma unroll 8
        for (int p = 0; p < 64; p++) {
            const float s = vt[p][lt] + trsT[p * 65 + n];
            if (s > m) { m = s; bi = p; }
        }
        g_bp[(size_t)t * LBL + n] = (unsigned char)bi;
    }
}

// ---------------------------------------------------------------------------
// Phase 3a: per-chunk composed backpointer maps (64-entry byte maps).
// ---------------------------------------------------------------------------
__global__ void __launch_bounds__(64)
maps_kernel(int T, int K)
{
    __shared__ unsigned char sbp[S_CH * LBL];
    const int c = blockIdx.x, tid = threadIdx.x;
    const int lo = c * S_CH + 1;
    const int hi = min((c + 1) * S_CH, T - 1);
    const int nrows = hi - lo + 1;

    const uint4* src = reinterpret_cast<const uint4*>(g_bp + (size_t)lo * LBL);
    uint4* dst = reinterpret_cast<uint4*>(sbp);
    for (int i = tid; i < nrows * 4; i += 64) dst[i] = src[i];
    __syncthreads();

    int m = tid;
    for (int j = nrows - 1; j >= 0; j--) m = sbp[j * LBL + m];
    g_H[c * LBL + tid] = (unsigned char)m;
}

// ---------------------------------------------------------------------------
// Phase 3b: terminal argmax + score, then serial chase over K chunk maps.
// ---------------------------------------------------------------------------
__global__ void __launch_bounds__(64)
chase_kernel(const float* __restrict__ trans, int T, int K,
             float* __restrict__ out, int out_size)
{
    __shared__ unsigned char sh[MAXK * LBL];
    const int tid = threadIdx.x;
    for (int i = tid; i < K * 4; i += 64)
        reinterpret_cast<uint4*>(sh)[i] = reinterpret_cast<const uint4*>(g_H)[i];
    __syncthreads();

    if (tid == 0) {
        // terminal = V[T] + transitions[STOP]; STOP = 63
        float m = -3.4e38f; int best = 0;
        for (int p = 0; p < 64; p++) {
            const float s = g_v2[(size_t)p * MAXT + (T - 1)] + trans[63 * 64 + p];
            if (s > m) { m = s; best = p; }
        }
        if (out_size > T) out[0] = m;   // path_score
        g_best = best;
        int e = best;                   // = path[T-1]
        for (int c = K - 1; c >= 1; c--) {
            e = sh[c * LBL + e];        // -> path[c*S]
            g_E[c] = e;
        }
    }
}

// ---------------------------------------------------------------------------
// Phase 3c: parallel fill. Chunk c writes path[j] for j in [c*S, hi).
// ---------------------------------------------------------------------------
__global__ void __launch_bounds__(64)
fill_kernel(int T, int K, float* __restrict__ out, int base)
{
    __shared__ unsigned char sbp[S_CH * LBL];
    const int c = blockIdx.x, tid = threadIdx.x;
    const int lo = c * S_CH + 1;
    const int hi = min((c + 1) * S_CH, T - 1);
    const int nrows = hi - lo + 1;

    const uint4* src = reinterpret_cast<const uint4*>(g_bp + (size_t)lo * LBL);
    uint4* dst = reinterpret_cast<uint4*>(sbp);
    for (int i = tid; i < nrows * 4; i += 64) dst[i] = src[i];
    __syncthreads();

    if (tid == 0) {
        int j, cur;
        if (c == K - 1) {
            cur = g_best;                       // path[T-1]
            out[base + T - 1] = (float)cur;
            j = T - 2;
        } else {
            const int x = g_E[c + 1];           // path[(c+1)*S]
            cur = sbp[(hi - lo) * LBL + x];     // bp[(c+1)*S][x] = path[hi-1]
            out[base + hi - 1] = (float)cur;
            j = hi - 2;
        }
        for (; j >= c * S_CH; j--) {
            cur = sbp[(j + 1 - lo) * LBL + cur];
            out[base + j] = (float)cur;
        }
    }
}

// ---------------------------------------------------------------------------
extern "C" void kernel_launch(void* const* d_in, const int* in_sizes, int n_in,
                              void* d_out, int out_size)
{
    const float* feats = (const float*)d_in[0];   // (1, T, 64) float32
    const float* trans = (const float*)d_in[1];   // (64, 64) float32
    float* out = (float*)d_out;

    const int T = in_sizes[0] / LBL;
    const int K = (T + S_CH - 1) / S_CH;
    const int base = (out_size > T) ? 1 : 0;

    fwd_kernel<<<1, 128>>>(feats, trans, T);

    const int nb = (T - 1 + 63) / 64;
    bp_kernel<<<nb, 256>>>(trans, T);

    maps_kernel<<<K, 64>>>(T, K);
    chase_kernel<<<1, 64>>>(trans, T, K, out, out_size);
    fill_kernel<<<K, 64>>>(T, K, out, base);
}

// round 10
// speedup vs baseline: 1.4814x; 1.4814x over previous
#include <cuda_runtime.h>

#define LBL   64
#define MAXT  200000
#define S_CH  500
#define MAXK  512

// scratch (static device globals — no allocation)
__device__ float         g_v[(size_t)MAXT * LBL];   // g_v[t] = V[t+1] (v AFTER step t)
__device__ unsigned char g_bp[(size_t)MAXT * LBL];  // bp rows, row 0 unused
__device__ unsigned char g_H[MAXK * LBL];           // per-chunk composed maps
__device__ int           g_E[MAXK + 2];             // boundary path values
__device__ int           g_best;

// ---------------------------------------------------------------------------
// Phase 1: serial forward pass. 1 block, 128 threads (4 warps, 1 per SMSP).
// warp w handles tags n = 16w..16w+15; 2 lanes per tag (q=0,1), 32 prevs/lane.
// v row layout (128 floats):
//   [0..63]   primary v[0..63]
//   [64..79]  REPLICA of v[32..47]
//   [80..127] park slots (48 distinct, never read)
// q=0 reads floats 0..31  (chunk j -> bank quad j)
// q=1 reads floats 48..79 (= v[48..63], v[32..47]; chunk j -> quad (j+4)&7)
//   -> every LDS.128 is conflict-free (R4 layout: 2-way conflict on all 8).
// Chunk rotation for q=1 is bit-exact (fmax assoc/comm, finite floats);
// transition registers loaded in matching rotated order at init.
// Store map (all 128 slots distinct — fixes the R9 write race):
//   q=0:            slot n
//   q=1, 32<=n<48:  slot n+32   (replica)
//   q=1, n<32:      slot 80+n   (park)
//   q=1, n>=48:     slot 112+(n-48) (park)
// One STS per lane; sbase computed once. Chain: LDS -> add/max tree -> +feat
// -> 1 SHFL -> FMNMX -> STS -> BAR(nw=4). Emission folded pre-shuffle
// (bit-exact: fmax(a+f,b+f) == fmax(a,b)+f, monotone rounding).
// Loop body instruction stream otherwise IDENTICAL to the 27.17ms R4 kernel
// (R5-R8: every other body change regressed — do not reapply).
// ---------------------------------------------------------------------------
__global__ void __launch_bounds__(128, 1)
fwd_kernel(const float* __restrict__ feats, const float* __restrict__ trans, int T)
{
    __shared__ __align__(16) float sv[2][128];
    __shared__ __align__(16) float fsh[2][64 * LBL];   // 2 x 16KB feat chunks

    const int tid  = threadIdx.x;
    const int w    = tid >> 5;
    const int lane = tid & 31;
    const int k    = lane >> 1;       // tag within warp (0..15)
    const int q    = lane & 1;        // prev-half (0: v[0..31], 1: v[48..63],v[32..47])
    const int n    = w * 16 + k;

    // transition segment in the lane's chunk order:
    // q=0 chunk j -> prevs 4j..4j+3                      -> float4 idx j
    // q=1 chunk j -> prevs 48+4j (j<4), 32+4(j-4) (j>=4) -> idx 12+j / 4+j
    const float4* trr = reinterpret_cast<const float4*>(trans + n * 64);
    const float4 t0 = trr[q ? 12 : 0];
    const float4 t1 = trr[q ? 13 : 1];
    const float4 t2 = trr[q ? 14 : 2];
    const float4 t3 = trr[q ? 15 : 3];
    const float4 t4 = trr[q ?  8 : 4];
    const float4 t5 = trr[q ?  9 : 5];
    const float4 t6 = trr[q ? 10 : 6];
    const float4 t7 = trr[q ? 11 : 7];

    // init both primary and replica (park slots don't matter but set anyway)
    if (tid < 128) {
        const int tag = (tid < 64) ? tid : ((tid < 80) ? (tid - 32) : -1);
        sv[0][tid] = (tag == 62) ? 0.0f : -10000.0f;   // START=62
    }

    const int nch = (T + 63) >> 6;
    const int totElems = T * LBL;
    const int rbase = q * 48;          // per-lane read base (floats)
    int sbase;                         // per-lane store slot (all distinct)
    if (q == 0)                sbase = n;
    else if (n >= 32 && n < 48) sbase = n + 32;       // replica of v[32..47]
    else if (n < 32)            sbase = 80 + n;       // park
    else                        sbase = 112 + (n - 48); // park

    // prefetch one 16KB chunk (64 steps) with cp.async
    auto prefetch = [&](int ch, int buf) {
        const float* src = feats + ch * 4096;
#pragma unroll
        for (int i = 0; i < 8; i++) {
            int e = tid + i * 128;                 // 16B units within chunk
            if (ch * 4096 + e * 4 + 3 < totElems) {
                unsigned saddr = (unsigned)__cvta_generic_to_shared(&fsh[buf][e * 4]);
                asm volatile("cp.async.cg.shared.global [%0], [%1], 16;"
                             :: "r"(saddr), "l"(src + e * 4));
            }
        }
        asm volatile("cp.async.commit_group;" ::: "memory");
    };

    prefetch(0, 0);
    if (nch > 1) prefetch(1, 1); else asm volatile("cp.async.commit_group;" ::: "memory");
    __syncthreads();

    for (int ch = 0; ch < nch; ch++) {
        asm volatile("cp.async.wait_group 1;" ::: "memory");
        __syncthreads();
        const float* fb  = fsh[ch & 1] + n;                      // imm offsets below
        float*       gvp = g_v + (size_t)(ch << 6) * LBL + n;    // imm offsets below
        const int steps = min(64, T - (ch << 6));
#pragma unroll 2
        for (int i = 0; i < steps; i++) {
            const int cur = i & 1;  // compile-time under unroll-2
            const float4* vv = reinterpret_cast<const float4*>(&sv[cur][rbase]);
            const float4 a0 = vv[0], a1 = vv[1], a2 = vv[2], a3 = vv[3];
            const float4 a4 = vv[4], a5 = vv[5], a6 = vv[6], a7 = vv[7];
            float m0 = fmaxf(fmaxf(a0.x + t0.x, a0.y + t0.y), fmaxf(a0.z + t0.z, a0.w + t0.w));
            float m1 = fmaxf(fmaxf(a1.x + t1.x, a1.y + t1.y), fmaxf(a1.z + t1.z, a1.w + t1.w));
            float m2 = fmaxf(fmaxf(a2.x + t2.x, a2.y + t2.y), fmaxf(a2.z + t2.z, a2.w + t2.w));
            float m3 = fmaxf(fmaxf(a3.x + t3.x, a3.y + t3.y), fmaxf(a3.z + t3.z, a3.w + t3.w));
            float m4 = fmaxf(fmaxf(a4.x + t4.x, a4.y + t4.y), fmaxf(a4.z + t4.z, a4.w + t4.w));
            float m5 = fmaxf(fmaxf(a5.x + t5.x, a5.y + t5.y), fmaxf(a5.z + t5.z, a5.w + t5.w));
            float m6 = fmaxf(fmaxf(a6.x + t6.x, a6.y + t6.y), fmaxf(a6.z + t6.z, a6.w + t6.w));
            float m7 = fmaxf(fmaxf(a7.x + t7.x, a7.y + t7.y), fmaxf(a7.z + t7.z, a7.w + t7.w));
            float mm = fmaxf(fmaxf(fmaxf(m0, m1), fmaxf(m2, m3)),
                             fmaxf(fmaxf(m4, m5), fmaxf(m6, m7)));
            // fold emission before the shuffle (bit-exact, see header comment)
            mm += fb[i << 6];
            const float other = __shfl_xor_sync(0xffffffffu, mm, 1);
            const float vn = fmaxf(mm, other);
            sv[cur ^ 1][sbase] = vn;           // chain store (primary/replica/park)
            if (q == 1) gvp[i * LBL] = vn;     // off-chain store (global)
            __syncthreads();
        }
        if (ch + 2 < nch) prefetch(ch + 2, ch & 1);
        else asm volatile("cp.async.commit_group;" ::: "memory");
    }
}

// ---------------------------------------------------------------------------
// Phase 2: recompute backpointers for all t in [1, T-1], fully parallel.
// block handles 16 consecutive t (4 at a time); thread = (tt, n). Strict '>'
// ascending p == jnp.argmax first-index tie-break. Bit-exact adds.
// ---------------------------------------------------------------------------
__global__ void __launch_bounds__(256)
bp_kernel(const float* __restrict__ trans, int T)
{
    __shared__ float trsT[64 * 65];   // transposed + padded: trsT[p*65+n]
    __shared__ float vsh[4][64];

    const int tid = threadIdx.x;
    for (int x = tid; x < 4096; x += 256) {
        int nn = x >> 6, pp = x & 63;
        trsT[pp * 65 + nn] = trans[x];
    }
    const int base_t = 1 + blockIdx.x * 16;
    const int tt = tid >> 6, n = tid & 63;

    for (int r = 0; r < 4; r++) {
        const int t = base_t + r * 4 + tt;
        __syncthreads();
        if (t <= T - 1) vsh[tt][n] = g_v[(size_t)(t - 1) * LBL + n];  // = V[t]
        __syncthreads();
        if (t > T - 1) continue;

        float m = -3.4e38f;
        int bi = 0;
#pragma unroll 8
        for (int p = 0; p < 64; p++) {
            float s = vsh[tt][p] + trsT[p * 65 + n];
            if (s > m) { m = s; bi = p; }
        }
        g_bp[(size_t)t * LBL + n] = (unsigned char)bi;
    }
}

// ---------------------------------------------------------------------------
// Phase 3a: per-chunk composed backpointer maps (64-entry byte maps).
// ---------------------------------------------------------------------------
__global__ void __launch_bounds__(64)
maps_kernel(int T, int K)
{
    __shared__ unsigned char sbp[S_CH * LBL];
    const int c = blockIdx.x, tid = threadIdx.x;
    const int lo = c * S_CH + 1;
    const int hi = min((c + 1) * S_CH, T - 1);
    const int nrows = hi - lo + 1;

    const uint4* src = reinterpret_cast<const uint4*>(g_bp + (size_t)lo * LBL);
    uint4* dst = reinterpret_cast<uint4*>(sbp);
    for (int i = tid; i < nrows * 4; i += 64) dst[i] = src[i];
    __syncthreads();

    int m = tid;
    for (int j = nrows - 1; j >= 0; j--) m = sbp[j * LBL + m];
    g_H[c * LBL + tid] = (unsigned char)m;
}

// ---------------------------------------------------------------------------
// Phase 3b: terminal argmax + score, then serial chase over K chunk maps.
// ---------------------------------------------------------------------------
__global__ void __launch_bounds__(64)
chase_kernel(const float* __restrict__ trans, int T, int K,
             float* __restrict__ out, int out_size)
{
    __shared__ unsigned char sh[MAXK * LBL];
    const int tid = threadIdx.x;
    for (int i = tid; i < K * 4; i += 64)
        reinterpret_cast<uint4*>(sh)[i] = reinterpret_cast<const uint4*>(g_H)[i];
    __syncthreads();

    if (tid == 0) {
        // terminal = V[T] + transitions[STOP]; STOP = 63
        float m = -3.4e38f; int best = 0;
        for (int p = 0; p < 64; p++) {
            float s = g_v[(size_t)(T - 1) * LBL + p] + trans[63 * 64 + p];
            if (s > m) { m = s; best = p; }
        }
        if (out_size > T) out[0] = m;   // path_score
        g_best = best;
        int e = best;                   // = path[T-1]
        for (int c = K - 1; c >= 1; c--) {
            e = sh[c * LBL + e];        // -> path[c*S]
            g_E[c] = e;
        }
    }
}

// ---------------------------------------------------------------------------
// Phase 3c: parallel fill. Chunk c writes path[j] for j in [c*S, hi).
// ---------------------------------------------------------------------------
__global__ void __launch_bounds__(64)
fill_kernel(int T, int K, float* __restrict__ out, int base)
{
    __shared__ unsigned char sbp[S_CH * LBL];
    const int c = blockIdx.x, tid = threadIdx.x;
    const int lo = c * S_CH + 1;
    const int hi = min((c + 1) * S_CH, T - 1);
    const int nrows = hi - lo + 1;

    const uint4* src = reinterpret_cast<const uint4*>(g_bp + (size_t)lo * LBL);
    uint4* dst = reinterpret_cast<uint4*>(sbp);
    for (int i = tid; i < nrows * 4; i += 64) dst[i] = src[i];
    __syncthreads();

    if (tid == 0) {
        int j, cur;
        if (c == K - 1) {
            cur = g_best;                       // path[T-1]
            out[base + T - 1] = (float)cur;
            j = T - 2;
        } else {
            const int x = g_E[c + 1];           // path[(c+1)*S]
            cur = sbp[(hi - lo) * LBL + x];     // bp[(c+1)*S][x] = path[hi-1]
            out[base + hi - 1] = (float)cur;
            j = hi - 2;
        }
        for (; j >= c * S_CH; j--) {
            cur = sbp[(j + 1 - lo) * LBL + cur];
            out[base + j] = (float)cur;
        }
    }
}

// ---------------------------------------------------------------------------
extern "C" void kernel_launch(void* const* d_in, const int* in_sizes, int n_in,
                              void* d_out, int out_size)
{
    const float* feats = (const float*)d_in[0];   // (1, T, 64) float32
    const float* trans = (const float*)d_in[1];   // (64, 64) float32
    float* out = (float*)d_out;

    const int T = in_sizes[0] / LBL;
    const int K = (T + S_CH - 1) / S_CH;
    const int base = (out_size > T) ? 1 : 0;

    fwd_kernel<<<1, 128>>>(feats, trans, T);

    const int nb = (T - 1 + 15) / 16;
    bp_kernel<<<nb, 256>>>(trans, T);

    maps_kernel<<<K, 64>>>(T, K);
    chase_kernel<<<1, 64>>>(trans, T, K, out, out_size);
    fill_kernel<<<K, 64>>>(T, K, out, base);
}

// round 11
// speedup vs baseline: 1.4824x; 1.0006x over previous
#include <cuda_runtime.h>

#define LBL   64
#define MAXT  200000
#define S_CH  500
#define MAXK  512

// scratch (static device globals — no allocation)
__device__ float         g_v[(size_t)MAXT * LBL];   // g_v[t] = V[t+1] (v AFTER step t)
__device__ unsigned char g_bp[(size_t)MAXT * LBL];  // bp rows, row 0 unused
__device__ unsigned char g_H[MAXK * LBL];           // per-chunk composed maps
__device__ int           g_E[MAXK + 2];             // boundary path values
__device__ int           g_best;

// ---------------------------------------------------------------------------
// Phase 1: serial forward pass. 1 block, 128 threads (4 warps, 1 per SMSP).
// warp w handles tags n = 16w..16w+15; 2 lanes per tag (q=0,1), 32 prevs/lane.
// v row layout (176 floats):
//   [0..63]    primary v[0..63]
//   [80..111]  park slots (written by q=1 lanes of tags 0..31, never read)
//   [144..175] REPLICA of v[32..63], natural order (read by q=1)
// LDS (per chunk j, one LDS.128, 2 broadcast addrs/warp):
//   q=0 reads floats 4j      -> bank quad j
//   q=1 reads floats 144+4j  -> bank quad (4+j)&7       => disjoint, 1 wavefront
//   (row stride 176 floats = 704B shifts row-1 quads uniformly by +4 — still ok)
// STS (per warp, 32 lanes, all banks distinct => 1 wavefront):
//   q=0 -> slot n; q=1 -> 80+n (n<32) or 112+n (n>=32)
//   w0: {0-15 | 16-31}, w1: {16-31 | 0-15}, w2: {0-15 | 16-31}, w3: {16-31 | 0-15}
//   (R10 had 2-way STS conflicts in warps 2,3 — this is the only change)
// Chain: LDS -> add/max tree -> +feat -> 1 SHFL -> FMNMX -> STS -> BAR(nw=4).
// Emission folded pre-shuffle (bit-exact: fmax(a+f,b+f)==fmax(a,b)+f, monotone
// rounding). Loop body instruction stream IDENTICAL to the 21.37ms R10 kernel.
// ---------------------------------------------------------------------------
__global__ void __launch_bounds__(128, 1)
fwd_kernel(const float* __restrict__ feats, const float* __restrict__ trans, int T)
{
    __shared__ __align__(16) float sv[2][176];
    __shared__ __align__(16) float fsh[2][64 * LBL];   // 2 x 16KB feat chunks

    const int tid  = threadIdx.x;
    const int w    = tid >> 5;
    const int lane = tid & 31;
    const int k    = lane >> 1;       // tag within warp (0..15)
    const int q    = lane & 1;        // prev-half (0: v[0..31], 1: v[32..63] via replica)
    const int n    = w * 16 + k;

    // transition segment T[n][q*32 .. q*32+31] (natural order, as in R4)
    const float4* trr = reinterpret_cast<const float4*>(trans + n * 64 + q * 32);
    const float4 t0 = trr[0], t1 = trr[1], t2 = trr[2], t3 = trr[3];
    const float4 t4 = trr[4], t5 = trr[5], t6 = trr[6], t7 = trr[7];

    // init primary [0..63] and replica [144..175] (parks never read)
    if (tid < 64) {
        sv[0][tid] = (tid == 62) ? 0.0f : -10000.0f;           // START=62
    } else if (tid < 96) {
        sv[0][tid + 80] = ((tid - 32) == 62) ? 0.0f : -10000.0f; // replica of v[32..63]
    }

    const int nch = (T + 63) >> 6;
    const int totElems = T * LBL;
    const int rbase = q ? 144 : 0;                  // per-lane read base (floats)
    const int sbase = q ? ((n < 32) ? (80 + n) : (112 + n)) : n;  // store slot

    // prefetch one 16KB chunk (64 steps) with cp.async
    auto prefetch = [&](int ch, int buf) {
        const float* src = feats + ch * 4096;
#pragma unroll
        for (int i = 0; i < 8; i++) {
            int e = tid + i * 128;                 // 16B units within chunk
            if (ch * 4096 + e * 4 + 3 < totElems) {
                unsigned saddr = (unsigned)__cvta_generic_to_shared(&fsh[buf][e * 4]);
                asm volatile("cp.async.cg.shared.global [%0], [%1], 16;"
                             :: "r"(saddr), "l"(src + e * 4));
            }
        }
        asm volatile("cp.async.commit_group;" ::: "memory");
    };

    prefetch(0, 0);
    if (nch > 1) prefetch(1, 1); else asm volatile("cp.async.commit_group;" ::: "memory");
    __syncthreads();

    for (int ch = 0; ch < nch; ch++) {
        asm volatile("cp.async.wait_group 1;" ::: "memory");
        __syncthreads();
        const float* fb  = fsh[ch & 1] + n;                      // imm offsets below
        float*       gvp = g_v + (size_t)(ch << 6) * LBL + n;    // imm offsets below
        const int steps = min(64, T - (ch << 6));
#pragma unroll 2
        for (int i = 0; i < steps; i++) {
            const int cur = i & 1;  // compile-time under unroll-2
            const float4* vv = reinterpret_cast<const float4*>(&sv[cur][rbase]);
            const float4 a0 = vv[0], a1 = vv[1], a2 = vv[2], a3 = vv[3];
            const float4 a4 = vv[4], a5 = vv[5], a6 = vv[6], a7 = vv[7];
            float m0 = fmaxf(fmaxf(a0.x + t0.x, a0.y + t0.y), fmaxf(a0.z + t0.z, a0.w + t0.w));
            float m1 = fmaxf(fmaxf(a1.x + t1.x, a1.y + t1.y), fmaxf(a1.z + t1.z, a1.w + t1.w));
            float m2 = fmaxf(fmaxf(a2.x + t2.x, a2.y + t2.y), fmaxf(a2.z + t2.z, a2.w + t2.w));
            float m3 = fmaxf(fmaxf(a3.x + t3.x, a3.y + t3.y), fmaxf(a3.z + t3.z, a3.w + t3.w));
            float m4 = fmaxf(fmaxf(a4.x + t4.x, a4.y + t4.y), fmaxf(a4.z + t4.z, a4.w + t4.w));
            float m5 = fmaxf(fmaxf(a5.x + t5.x, a5.y + t5.y), fmaxf(a5.z + t5.z, a5.w + t5.w));
            float m6 = fmaxf(fmaxf(a6.x + t6.x, a6.y + t6.y), fmaxf(a6.z + t6.z, a6.w + t6.w));
            float m7 = fmaxf(fmaxf(a7.x + t7.x, a7.y + t7.y), fmaxf(a7.z + t7.z, a7.w + t7.w));
            float mm = fmaxf(fmaxf(fmaxf(m0, m1), fmaxf(m2, m3)),
                             fmaxf(fmaxf(m4, m5), fmaxf(m6, m7)));
            // fold emission before the shuffle (bit-exact, see header comment)
            mm += fb[i << 6];
            const float other = __shfl_xor_sync(0xffffffffu, mm, 1);
            const float vn = fmaxf(mm, other);
            sv[cur ^ 1][sbase] = vn;           // chain store (primary/park/replica)
            if (q == 1) gvp[i * LBL] = vn;     // off-chain store (global)
            __syncthreads();
        }
        if (ch + 2 < nch) prefetch(ch + 2, ch & 1);
        else asm volatile("cp.async.commit_group;" ::: "memory");
    }
}

// ---------------------------------------------------------------------------
// Phase 2: recompute backpointers for all t in [1, T-1], fully parallel.
// block handles 16 consecutive t (4 at a time); thread = (tt, n). Strict '>'
// ascending p == jnp.argmax first-index tie-break. Bit-exact adds.
// ---------------------------------------------------------------------------
__global__ void __launch_bounds__(256)
bp_kernel(const float* __restrict__ trans, int T)
{
    __shared__ float trsT[64 * 65];   // transposed + padded: trsT[p*65+n]
    __shared__ float vsh[4][64];

    const int tid = threadIdx.x;
    for (int x = tid; x < 4096; x += 256) {
        int nn = x >> 6, pp = x & 63;
        trsT[pp * 65 + nn] = trans[x];
    }
    const int base_t = 1 + blockIdx.x * 16;
    const int tt = tid >> 6, n = tid & 63;

    for (int r = 0; r < 4; r++) {
        const int t = base_t + r * 4 + tt;
        __syncthreads();
        if (t <= T - 1) vsh[tt][n] = g_v[(size_t)(t - 1) * LBL + n];  // = V[t]
        __syncthreads();
        if (t > T - 1) continue;

        float m = -3.4e38f;
        int bi = 0;
#pragma unroll 8
        for (int p = 0; p < 64; p++) {
            float s = vsh[tt][p] + trsT[p * 65 + n];
            if (s > m) { m = s; bi = p; }
        }
        g_bp[(size_t)t * LBL + n] = (unsigned char)bi;
    }
}

// ---------------------------------------------------------------------------
// Phase 3a: per-chunk composed backpointer maps (64-entry byte maps).
// ---------------------------------------------------------------------------
__global__ void __launch_bounds__(64)
maps_kernel(int T, int K)
{
    __shared__ unsigned char sbp[S_CH * LBL];
    const int c = blockIdx.x, tid = threadIdx.x;
    const int lo = c * S_CH + 1;
    const int hi = min((c + 1) * S_CH, T - 1);
    const int nrows = hi - lo + 1;

    const uint4* src = reinterpret_cast<const uint4*>(g_bp + (size_t)lo * LBL);
    uint4* dst = reinterpret_cast<uint4*>(sbp);
    for (int i = tid; i < nrows * 4; i += 64) dst[i] = src[i];
    __syncthreads();

    int m = tid;
    for (int j = nrows - 1; j >= 0; j--) m = sbp[j * LBL + m];
    g_H[c * LBL + tid] = (unsigned char)m;
}

// ---------------------------------------------------------------------------
// Phase 3b: terminal argmax + score, then serial chase over K chunk maps.
// ---------------------------------------------------------------------------
__global__ void __launch_bounds__(64)
chase_kernel(const float* __restrict__ trans, int T, int K,
             float* __restrict__ out, int out_size)
{
    __shared__ unsigned char sh[MAXK * LBL];
    const int tid = threadIdx.x;
    for (int i = tid; i < K * 4; i += 64)
        reinterpret_cast<uint4*>(sh)[i] = reinterpret_cast<const uint4*>(g_H)[i];
    __syncthreads();

    if (tid == 0) {
        // terminal = V[T] + transitions[STOP]; STOP = 63
        float m = -3.4e38f; int best = 0;
        for (int p = 0; p < 64; p++) {
            float s = g_v[(size_t)(T - 1) * LBL + p] + trans[63 * 64 + p];
            if (s > m) { m = s; best = p; }
        }
        if (out_size > T) out[0] = m;   // path_score
        g_best = best;
        int e = best;                   // = path[T-1]
        for (int c = K - 1; c >= 1; c--) {
            e = sh[c * LBL + e];        // -> path[c*S]
            g_E[c] = e;
        }
    }
}

// ---------------------------------------------------------------------------
// Phase 3c: parallel fill. Chunk c writes path[j] for j in [c*S, hi).
// ---------------------------------------------------------------------------
__global__ void __launch_bounds__(64)
fill_kernel(int T, int K, float* __restrict__ out, int base)
{
    __shared__ unsigned char sbp[S_CH * LBL];
    const int c = blockIdx.x, tid = threadIdx.x;
    const int lo = c * S_CH + 1;
    const int hi = min((c + 1) * S_CH, T - 1);
    const int nrows = hi - lo + 1;

    const uint4* src = reinterpret_cast<const uint4*>(g_bp + (size_t)lo * LBL);
    uint4* dst = reinterpret_cast<uint4*>(sbp);
    for (int i = tid; i < nrows * 4; i += 64) dst[i] = src[i];
    __syncthreads();

    if (tid == 0) {
        int j, cur;
        if (c == K - 1) {
            cur = g_best;                       // path[T-1]
            out[base + T - 1] = (float)cur;
            j = T - 2;
        } else {
            const int x = g_E[c + 1];           // path[(c+1)*S]
            cur = sbp[(hi - lo) * LBL + x];     // bp[(c+1)*S][x] = path[hi-1]
            out[base + hi - 1] = (float)cur;
            j = hi - 2;
        }
        for (; j >= c * S_CH; j--) {
            cur = sbp[(j + 1 - lo) * LBL + cur];
            out[base + j] = (float)cur;
        }
    }
}

// ---------------------------------------------------------------------------
extern "C" void kernel_launch(void* const* d_in, const int* in_sizes, int n_in,
                              void* d_out, int out_size)
{
    const float* feats = (const float*)d_in[0];   // (1, T, 64) float32
    const float* trans = (const float*)d_in[1];   // (64, 64) float32
    float* out = (float*)d_out;

    const int T = in_sizes[0] / LBL;
    const int K = (T + S_CH - 1) / S_CH;
    const int base = (out_size > T) ? 1 : 0;

    fwd_kernel<<<1, 128>>>(feats, trans, T);

    const int nb = (T - 1 + 15) / 16;
    bp_kernel<<<nb, 256>>>(trans, T);

    maps_kernel<<<K, 64>>>(T, K);
    chase_kernel<<<1, 64>>>(trans, T, K, out, out_size);
    fill_kernel<<<K, 64>>>(T, K, out, base);
}